// round 4
// baseline (speedup 1.0000x reference)
#include <cuda_runtime.h>
#include <cuda_bf16.h>
#include <cstdint>

// VQ-VAE quantization: bf16 mma.sync (HMMA) scoring + exact fp32 rescore.
// N=262144, K=1024, D=64. Output fp32: [0,N): Z, [N,N+N*D): q_with_st, +2 losses.

#define NROWS  262144
#define KMAX   1024
#define DDIM   64
#define BM     512          // rows per block
#define NT     256          // threads per block (8 warps)
#define RPW    64           // rows per warp
#define NTILES (KMAX / 8)   // 128 n-tiles of 8 codes
#define TAU    0.35f
#define CAP    20

__device__ double g_loss_accum;
__device__ float  g_csq[KMAX];
__device__ float  g_xsq[NROWS];
__device__ __align__(16) __nv_bfloat16 g_cbbf[KMAX * DDIM];
__device__ __align__(16) __nv_bfloat16 g_xbf[(size_t)NROWS * DDIM];

// ---------------------------------------------------------------------------
__device__ __forceinline__ uint32_t smem_u32(const void* p) {
    uint32_t a;
    asm("{ .reg .u64 t; cvta.to.shared.u64 t, %1; cvt.u32.u64 %0, t; }" : "=r"(a) : "l"(p));
    return a;
}
__device__ __forceinline__ void ldsm_x4(uint32_t r[4], uint32_t addr) {
    asm volatile("ldmatrix.sync.aligned.m8n8.x4.shared.b16 {%0,%1,%2,%3}, [%4];"
                 : "=r"(r[0]), "=r"(r[1]), "=r"(r[2]), "=r"(r[3]) : "r"(addr));
}
__device__ __forceinline__ void ldsm_x2(uint32_t r[2], uint32_t addr) {
    asm volatile("ldmatrix.sync.aligned.m8n8.x2.shared.b16 {%0,%1}, [%2];"
                 : "=r"(r[0]), "=r"(r[1]) : "r"(addr));
}
__device__ __forceinline__ void mma16816(float d[4], const uint32_t a[4], const uint32_t b[2]) {
    asm volatile("mma.sync.aligned.m16n8k16.row.col.f32.bf16.bf16.f32 "
                 "{%0,%1,%2,%3}, {%4,%5,%6,%7}, {%8,%9}, {%0,%1,%2,%3};"
                 : "+f"(d[0]), "+f"(d[1]), "+f"(d[2]), "+f"(d[3])
                 : "r"(a[0]), "r"(a[1]), "r"(a[2]), "r"(a[3]), "r"(b[0]), "r"(b[1]));
}
__device__ __forceinline__ uint32_t pack_bf2(float a, float b) {
    uint32_t lo = (uint32_t)__bfloat16_as_ushort(__float2bfloat16_rn(a));
    uint32_t hi = (uint32_t)__bfloat16_as_ushort(__float2bfloat16_rn(b));
    return lo | (hi << 16);
}

// ---------------------------------------------------------------------------
// prep kernels
// ---------------------------------------------------------------------------
__global__ void zero_kernel() { g_loss_accum = 0.0; }

__global__ void prep_cb_kernel(const float* __restrict__ cb, int K) {
    int k = blockIdx.x * blockDim.x + threadIdx.x;
    if (k >= K) return;
    float s = 0.f;
    #pragma unroll
    for (int d = 0; d < DDIM; d++) {
        float v = cb[(size_t)k * DDIM + d];
        s += v * v;
        g_cbbf[k * DDIM + d] = __float2bfloat16_rn(v);
    }
    g_csq[k] = s;
}

__global__ void prep_xbf_kernel(const float* __restrict__ x, int total_u4) {
    for (int i = blockIdx.x * blockDim.x + threadIdx.x; i < total_u4;
         i += gridDim.x * blockDim.x) {
        const float4* src = (const float4*)x + (size_t)i * 2;
        float4 a = src[0], b = src[1];
        uint4 o;
        o.x = pack_bf2(a.x, a.y); o.y = pack_bf2(a.z, a.w);
        o.z = pack_bf2(b.x, b.y); o.w = pack_bf2(b.z, b.w);
        ((uint4*)g_xbf)[i] = o;
    }
}

__global__ void prep_xsq_kernel(const float* __restrict__ x) {
    __shared__ float sx[128 * DDIM];
    int tid = threadIdx.x;
    size_t base = (size_t)blockIdx.x * 128 * DDIM;
    #pragma unroll
    for (int t = 0; t < (128 * DDIM) / (256 * 4); t++) {
        int lin = tid + t * 256;
        *((float4*)sx + lin) = *((const float4*)(x + base) + lin);
    }
    __syncthreads();
    if (tid < 128) {
        float s = 0.f;
        #pragma unroll
        for (int d = 0; d < DDIM; d++) {
            float v = sx[tid * DDIM + d];
            s += v * v;
        }
        g_xsq[blockIdx.x * 128 + tid] = s;
    }
}

__global__ void finalize_kernel(float* __restrict__ out, int N) {
    double mean = g_loss_accum / ((double)N * (double)DDIM);
    size_t base = (size_t)N + (size_t)N * DDIM;
    out[base]     = (float)mean;
    out[base + 1] = (float)mean;
}

// ---------------------------------------------------------------------------
// main kernel — smem layout (bytes)
// ---------------------------------------------------------------------------
#define OFF_A    0        // 65536  A bf16 [512 rows x 128B], 16B-chunk XOR swizzle
#define OFF_B    65536    // 131072 codebook bf16 [1024 x 128B], same swizzle
#define OFF_CSQ  196608   // 4096   csq fp32
#define OFF_CAND 200704   // 20480  u16 cand[512][20]    (aliased as dred later)
#define OFF_CNT  221184   // 2048   int cnt[512]
#define OFF_ZSH  223232   // 2048   int zsh[512]
#define SMEM_BYTES 225280

__global__ __launch_bounds__(NT, 1)
void vq_main_kernel(const float* __restrict__ x, const float* __restrict__ cb,
                    float* __restrict__ out, int N, int K) {
    extern __shared__ char smem[];
    const uint32_t smb = smem_u32(smem);
    float*          csq_s = (float*)(smem + OFF_CSQ);
    unsigned short* cand  = (unsigned short*)(smem + OFF_CAND);
    int*            cnt   = (int*)(smem + OFF_CNT);
    int*            zsh   = (int*)(smem + OFF_ZSH);

    const int tid  = threadIdx.x;
    const int wid  = tid >> 5;
    const int lane = tid & 31;
    const int rowBase = blockIdx.x * BM;
    const int wbase   = wid * RPW;

    // ---- cooperative fills (swizzled 16B chunks) ----
    #pragma unroll
    for (int i = 0; i < (BM * 8) / NT; i++) {          // A: 512 rows x 8 chunks
        int lin = tid + i * NT;
        int r = lin >> 3, c = lin & 7;
        uint4 v = ((const uint4*)g_xbf)[(size_t)(rowBase + r) * 8 + c];
        *(uint4*)(smem + OFF_A + r * 128 + ((c ^ (r & 7)) << 4)) = v;
    }
    #pragma unroll
    for (int i = 0; i < (KMAX * 8) / NT; i++) {        // B: 1024 rows x 8 chunks
        int lin = tid + i * NT;
        int r = lin >> 3, c = lin & 7;
        uint4 v = ((const uint4*)g_cbbf)[(size_t)r * 8 + c];
        *(uint4*)(smem + OFF_B + r * 128 + ((c ^ (r & 7)) << 4)) = v;
    }
    #pragma unroll
    for (int i = 0; i < KMAX / NT; i++) csq_s[tid + i * NT] = g_csq[tid + i * NT];
    #pragma unroll
    for (int i = 0; i < BM / NT; i++) cnt[tid + i * NT] = 0;
    __syncthreads();

    // ---- A fragments: 4 m16-tiles x 4 k-steps, kept in registers ----
    uint32_t afr[4][4][4];
    #pragma unroll
    for (int m = 0; m < 4; m++)
        #pragma unroll
        for (int s = 0; s < 4; s++) {
            int r = wbase + m * 16 + (lane & 15);
            int c = 2 * s + (lane >> 4);
            ldsm_x4(afr[m][s], smb + OFF_A + r * 128 + ((c ^ (r & 7)) << 4));
        }

    float bv[8];
    #pragma unroll
    for (int i = 0; i < 8; i++) bv[i] = 3.4e38f;

    const int qrow = lane >> 2;        // fragment row 0..7
    const int qc   = (lane & 3) * 2;   // fragment col pair

    // ---- mainloop over 128 n-tiles of 8 codes ----
    #pragma unroll 1
    for (int j = 0; j < NTILES; j++) {
        uint32_t bfr[4][2];
        int brow  = j * 8 + (lane & 7);
        int bhalf = (lane >> 3) & 1;
        #pragma unroll
        for (int s = 0; s < 4; s++) {
            int c = 2 * s + bhalf;
            ldsm_x2(bfr[s], smb + OFF_B + brow * 128 + ((c ^ (brow & 7)) << 4));
        }
        float2 cs = *(const float2*)(csq_s + j * 8 + qc);
        int code0 = j * 8 + qc;

        #pragma unroll
        for (int m = 0; m < 4; m++) {
            float d[4] = {0.f, 0.f, 0.f, 0.f};
            #pragma unroll
            for (int s = 0; s < 4; s++) mma16816(d, afr[m][s], bfr[s]);

            int r0 = wbase + m * 16 + qrow;
            int r1 = r0 + 8;
            float sc0 = fmaf(-2.f, d[0], cs.x);
            float sc1 = fmaf(-2.f, d[1], cs.y);
            float sc2 = fmaf(-2.f, d[2], cs.x);
            float sc3 = fmaf(-2.f, d[3], cs.y);

            float t0 = bv[2 * m] + TAU, t1 = bv[2 * m + 1] + TAU;
            if (sc0 < t0) { int p = atomicAdd(&cnt[r0], 1); if (p < CAP) cand[r0 * CAP + p] = (unsigned short)code0; }
            if (sc1 < t0) { int p = atomicAdd(&cnt[r0], 1); if (p < CAP) cand[r0 * CAP + p] = (unsigned short)(code0 + 1); }
            if (sc2 < t1) { int p = atomicAdd(&cnt[r1], 1); if (p < CAP) cand[r1 * CAP + p] = (unsigned short)code0; }
            if (sc3 < t1) { int p = atomicAdd(&cnt[r1], 1); if (p < CAP) cand[r1 * CAP + p] = (unsigned short)(code0 + 1); }
            bv[2 * m]     = fminf(bv[2 * m],     fminf(sc0, sc1));
            bv[2 * m + 1] = fminf(bv[2 * m + 1], fminf(sc2, sc3));
        }

        if ((j & 3) == 3) {            // quad-share running mins (tighter threshold)
            #pragma unroll
            for (int i = 0; i < 8; i++) {
                bv[i] = fminf(bv[i], __shfl_xor_sync(0xffffffffu, bv[i], 1));
                bv[i] = fminf(bv[i], __shfl_xor_sync(0xffffffffu, bv[i], 2));
            }
        }
    }
    __syncthreads();

    // ---- exact fp32 rescore (reference formula, sequential-d fma) ----
    #pragma unroll 1
    for (int rr = 0; rr < 2; rr++) {
        int row = tid + rr * NT;
        int c   = cnt[row];
        if (c > CAP) continue;                      // handled by warp pass
        int grow = rowBase + row;
        float xr[DDIM];
        const float4* xp = (const float4*)(x + (size_t)grow * DDIM);
        #pragma unroll
        for (int g = 0; g < 16; g++) {
            float4 v = xp[g];
            xr[4 * g] = v.x; xr[4 * g + 1] = v.y; xr[4 * g + 2] = v.z; xr[4 * g + 3] = v.w;
        }
        float xq = g_xsq[grow];
        float best = 3.4e38f; int bz = 0;
        #pragma unroll 1
        for (int t = 0; t < c; t++) {
            int idx = cand[row * CAP + t];
            const float4* cp = (const float4*)(cb + (size_t)idx * DDIM);
            float dot = 0.f;
            #pragma unroll
            for (int g = 0; g < 16; g++) {
                float4 cv = cp[g];
                dot = fmaf(xr[4 * g],     cv.x, dot);
                dot = fmaf(xr[4 * g + 1], cv.y, dot);
                dot = fmaf(xr[4 * g + 2], cv.z, dot);
                dot = fmaf(xr[4 * g + 3], cv.w, dot);
            }
            float sc = (xq - 2.0f * dot) + csq_s[idx];
            if (sc < best || (sc == best && idx < bz)) { best = sc; bz = idx; }
        }
        zsh[row] = bz;
        out[grow] = (float)bz;
    }

    // ---- overflow rows: exact exhaustive, warp-parallel (rare) ----
    #pragma unroll 1
    for (int r = wbase; r < wbase + RPW; r++) {
        if (cnt[r] <= CAP) continue;
        int grow = rowBase + r;
        float xr[DDIM];
        const float4* xp = (const float4*)(x + (size_t)grow * DDIM);
        #pragma unroll
        for (int g = 0; g < 16; g++) {
            float4 v = xp[g];
            xr[4 * g] = v.x; xr[4 * g + 1] = v.y; xr[4 * g + 2] = v.z; xr[4 * g + 3] = v.w;
        }
        float xq = g_xsq[grow];
        float best = 3.4e38f; int bz = KMAX;
        #pragma unroll 1
        for (int k = lane; k < KMAX; k += 32) {
            const float4* cp = (const float4*)(cb + (size_t)k * DDIM);
            float dot = 0.f;
            #pragma unroll
            for (int g = 0; g < 16; g++) {
                float4 cv = cp[g];
                dot = fmaf(xr[4 * g],     cv.x, dot);
                dot = fmaf(xr[4 * g + 1], cv.y, dot);
                dot = fmaf(xr[4 * g + 2], cv.z, dot);
                dot = fmaf(xr[4 * g + 3], cv.w, dot);
            }
            float sc = (xq - 2.0f * dot) + csq_s[k];
            if (sc < best) { best = sc; bz = k; }   // ascending k: first idx wins ties
        }
        #pragma unroll
        for (int o = 16; o > 0; o >>= 1) {
            float v  = __shfl_xor_sync(0xffffffffu, best, o);
            int   i2 = __shfl_xor_sync(0xffffffffu, bz, o);
            if (v < best || (v == best && i2 < bz)) { best = v; bz = i2; }
        }
        if (lane == 0) { zsh[r] = bz; out[grow] = (float)bz; }
    }
    __syncthreads();

    // ---- epilogue: q_with_st + loss (coalesced) ----
    double lsum = 0.0;
    const size_t qbase = (size_t)N;
    #pragma unroll
    for (int t = 0; t < (BM * DDIM) / (NT * 4); t++) {   // 32 float4 iters
        int lin4 = tid + t * NT;
        int r    = lin4 >> 4;
        int dq   = (lin4 & 15) << 2;
        int z    = zsh[r];
        float4 xv = *(const float4*)(x  + (size_t)(rowBase + r) * DDIM + dq);
        float4 qv = *(const float4*)(cb + (size_t)z * DDIM + dq);
        float dx = qv.x - xv.x, dy = qv.y - xv.y, dz = qv.z - xv.z, dw = qv.w - xv.w;
        *(float4*)(out + qbase + (size_t)(rowBase + r) * DDIM + dq) =
            make_float4(xv.x + dx, xv.y + dy, xv.z + dz, xv.w + dw);
        lsum += (double)dx * dx + (double)dy * dy + (double)dz * dz + (double)dw * dw;
    }
    double* dred = (double*)(smem + OFF_CAND);   // alias: cand dead now
    dred[tid] = lsum;
    __syncthreads();
    #pragma unroll
    for (int s = 128; s > 0; s >>= 1) {
        if (tid < s) dred[tid] += dred[tid + s];
        __syncthreads();
    }
    if (tid == 0) atomicAdd(&g_loss_accum, dred[0]);
}

// ---------------------------------------------------------------------------
extern "C" void kernel_launch(void* const* d_in, const int* in_sizes, int n_in,
                              void* d_out, int out_size) {
    const float* x  = (const float*)d_in[0];
    const float* cb = (const float*)d_in[1];
    float* out = (float*)d_out;

    int N = in_sizes[0] / DDIM;   // 262144
    int K = in_sizes[1] / DDIM;   // 1024

    cudaFuncSetAttribute(vq_main_kernel,
                         cudaFuncAttributeMaxDynamicSharedMemorySize, SMEM_BYTES);

    zero_kernel<<<1, 1>>>();
    prep_cb_kernel<<<(K + 127) / 128, 128>>>(cb, K);
    prep_xbf_kernel<<<2048, 256>>>(x, N * DDIM / 8);
    prep_xsq_kernel<<<N / 128, 256>>>(x);
    vq_main_kernel<<<N / BM, NT, SMEM_BYTES>>>(x, cb, out, N, K);
    finalize_kernel<<<1, 1>>>(out, N);
}

// round 5
// speedup vs baseline: 9.7805x; 9.7805x over previous
#include <cuda_runtime.h>
#include <cstdint>

// VQ-VAE codebook quantization, fused fp32 GEMM + argmin + gather + loss.
// N=262144 rows (x), K=1024 codes, D=64.
// Output layout (fp32): [0,N): Z (as float), [N, N+N*D): q_with_st, then 2 losses.
//
// R5: FMA2-issue-bound. Block tile 256 rows x 128 codes, 256 threads.
// Per-thread 16 rows x 8 codes (8 row-pair f32x2 accumulators x 8 codes).
// B tile stored DUPLICATED ({c,c} pairs) so both A and B stream via LDS.128:
// per d-step per thread = 4 LDS.128 (A) + 4 LDS.128 (B) + 64 fma2 = 72 issues.

#define DDIM 64
#define BM 256       // rows per block
#define BK 128       // codes per chunk
#define NT 256

__device__ double g_loss_accum;
__device__ float  g_csq[4096];

// ---------------------------------------------------------------------------
__global__ void csq_kernel(const float* __restrict__ cb, int K) {
    int k = blockIdx.x * blockDim.x + threadIdx.x;
    if (k < K) {
        float s = 0.f;
        #pragma unroll
        for (int d = 0; d < DDIM; d++) {
            float v = cb[(size_t)k * DDIM + d];
            s += v * v;
        }
        g_csq[k] = s;
    }
}

__global__ void zero_kernel() { g_loss_accum = 0.0; }

__global__ void finalize_kernel(float* __restrict__ out, int N) {
    double mean = g_loss_accum / ((double)N * (double)DDIM);
    size_t base = (size_t)N + (size_t)N * DDIM;
    out[base]     = (float)mean;  // vq_loss
    out[base + 1] = (float)mean;  // commitment_loss (numerically identical)
}

// ---------------------------------------------------------------------------
__device__ __forceinline__ unsigned long long fma2(unsigned long long a,
                                                   unsigned long long b,
                                                   unsigned long long c) {
    unsigned long long d;
    asm("fma.rn.f32x2 %0, %1, %2, %3;" : "=l"(d) : "l"(a), "l"(b), "l"(c));
    return d;
}
__device__ __forceinline__ float2 unpack2(unsigned long long v) {
    float2 f;
    asm("mov.b64 {%0, %1}, %2;" : "=f"(f.x), "=f"(f.y) : "l"(v));
    return f;
}

// Shared memory layout (floats):
//   As   [64][256]   x tile transposed (d-major)            16384
//   Bs2  [64][256]   code chunk, d-major, values DUPLICATED 16384
//                    (Bs2[d][2c] = Bs2[d][2c+1] = code[c][d], c in 0..127)
//   xsq  [256]
//   csq  [128]
//   rvs  [256][16]   running min value per (row, tx)         4096
//   ris  [256][16]   running min index                       4096 (int)
//   zsh  [256]       final argmin per row                    (int)
//   dred [256]       double reduce                           512 float-slots
#define OFF_AS   0
#define OFF_BS   (64*256)
#define OFF_XSQ  (OFF_BS + 64*256)
#define OFF_CSQ  (OFF_XSQ + 256)
#define OFF_RVS  (OFF_CSQ + 128)
#define OFF_RIS  (OFF_RVS + 4096)
#define OFF_ZSH  (OFF_RIS + 4096)
#define OFF_DRED (OFF_ZSH + 256)
#define SMEM_FLOATS (OFF_DRED + 512)

__global__ __launch_bounds__(NT, 1)
void vq_main_kernel(const float* __restrict__ x, const float* __restrict__ cb,
                    float* __restrict__ out, int N, int K) {
    extern __shared__ float smem[];
    float*  As    = smem + OFF_AS;
    float*  Bs2   = smem + OFF_BS;
    float*  xsq_s = smem + OFF_XSQ;
    float*  csq_s = smem + OFF_CSQ;
    float*  rvs   = smem + OFF_RVS;
    int*    ris   = (int*)(smem + OFF_RIS);
    int*    zsh   = (int*)(smem + OFF_ZSH);
    double* dred  = (double*)(smem + OFF_DRED);

    const int tid = threadIdx.x;
    const int tx  = tid & 15;    // code lane: owns codes tx*8 .. tx*8+7 of chunk
    const int ty  = tid >> 4;    // row group: rows ty*16 .. ty*16+15
    const int rowBase = blockIdx.x * BM;

    // ---- load x tile transposed: As[d][row] ----
    #pragma unroll
    for (int t = 0; t < (BM * DDIM) / (NT * 4); t++) {   // 16 iters of float4
        int lin = tid + t * NT;            // 0..4095
        int row = lin >> 4;
        int dg  = (lin & 15) << 2;
        float4 v = *(const float4*)(x + (size_t)(rowBase + row) * DDIM + dg);
        As[(dg + 0) * BM + row] = v.x;
        As[(dg + 1) * BM + row] = v.y;
        As[(dg + 2) * BM + row] = v.z;
        As[(dg + 3) * BM + row] = v.w;
    }
    // init running-min arrays: 4096 entries, 16 per thread
    #pragma unroll
    for (int t = 0; t < 16; t++) {
        rvs[tid + t * NT] = 3.4e38f;
        ris[tid + t * NT] = 0;
    }
    __syncthreads();

    // ---- x_sq per row (sequential over d — matches reference formula class) ----
    {
        float s = 0.f;
        #pragma unroll
        for (int d = 0; d < DDIM; d++) {
            float v = As[d * BM + tid];
            s += v * v;
        }
        xsq_s[tid] = s;
    }

    #pragma unroll 1
    for (int cbase = 0; cbase < K; cbase += BK) {
        __syncthreads();   // previous chunk fully consumed before overwriting Bs2

        // ---- load code chunk, d-major + duplicated: Bs2[d][2c] = Bs2[d][2c+1] = c[d]
        #pragma unroll
        for (int t = 0; t < (BK * DDIM) / (NT * 4); t++) {   // 8 iters of float4
            int lin  = tid + t * NT;         // 0..2047
            int code = lin >> 4;             // 0..127
            int dg   = (lin & 15) << 2;      // 0..60
            float4 v = *(const float4*)(cb + (size_t)(cbase + code) * DDIM + dg);
            *(float2*)&Bs2[(dg + 0) * 256 + 2 * code] = make_float2(v.x, v.x);
            *(float2*)&Bs2[(dg + 1) * 256 + 2 * code] = make_float2(v.y, v.y);
            *(float2*)&Bs2[(dg + 2) * 256 + 2 * code] = make_float2(v.z, v.z);
            *(float2*)&Bs2[(dg + 3) * 256 + 2 * code] = make_float2(v.w, v.w);
        }
        if (tid < BK) csq_s[tid] = g_csq[cbase + tid];
        __syncthreads();

        // ---- mainloop: 16 rows (8 f32x2 pairs) x 8 codes per thread ----
        unsigned long long acc[8][8];
        #pragma unroll
        for (int p = 0; p < 8; p++)
            #pragma unroll
            for (int j = 0; j < 8; j++) acc[p][j] = 0ULL;

        const float* aBase = As  + ty * 16;   // 64B-aligned
        const float* bBase = Bs2 + tx * 16;   // 64B-aligned (codes 8tx.., dup'd)

        #pragma unroll 8
        for (int d = 0; d < DDIM; d++) {
            const ulonglong2* ar = (const ulonglong2*)(aBase + d * BM);
            const ulonglong2* br = (const ulonglong2*)(bBase + d * 256);
            ulonglong2 A0 = ar[0], A1 = ar[1], A2 = ar[2], A3 = ar[3];
            ulonglong2 B0 = br[0], B1 = br[1], B2 = br[2], B3 = br[3];
            unsigned long long ap[8] = {A0.x, A0.y, A1.x, A1.y, A2.x, A2.y, A3.x, A3.y};
            unsigned long long bp[8] = {B0.x, B0.y, B1.x, B1.y, B2.x, B2.y, B3.x, B3.y};
            #pragma unroll
            for (int p = 0; p < 8; p++)
                #pragma unroll
                for (int j = 0; j < 8; j++)
                    acc[p][j] = fma2(ap[p], bp[j], acc[p][j]);
        }

        // ---- distances + per-chunk argmin, merge into persistent smem ----
        float cs[8];
        #pragma unroll
        for (int j = 0; j < 8; j++) cs[j] = csq_s[tx * 8 + j];

        #pragma unroll
        for (int p = 0; p < 8; p++) {
            int r0 = ty * 16 + 2 * p;
            float xq0 = xsq_s[r0];
            float xq1 = xsq_s[r0 + 1];
            float bv0 = 3.4e38f, bv1 = 3.4e38f;
            int   bi0 = 0,       bi1 = 0;
            #pragma unroll
            for (int j = 0; j < 8; j++) {       // ascending code index
                float2 dd = unpack2(acc[p][j]);
                float d0 = (xq0 - 2.0f * dd.x) + cs[j];
                float d1 = (xq1 - 2.0f * dd.y) + cs[j];
                int code = cbase + tx * 8 + j;
                if (d0 < bv0) { bv0 = d0; bi0 = code; }
                if (d1 < bv1) { bv1 = d1; bi1 = code; }
            }
            int s0 = r0 * 16 + tx;
            int s1 = s0 + 16;
            if (bv0 < rvs[s0]) { rvs[s0] = bv0; ris[s0] = bi0; }   // strict <: chunks ascend
            if (bv1 < rvs[s1]) { rvs[s1] = bv1; ris[s1] = bi1; }
        }
    }

    // ---- cross-tx argmin reduce: thread tid owns row tid ----
    __syncthreads();
    {
        float bv = rvs[tid * 16];
        int   bi = ris[tid * 16];
        #pragma unroll
        for (int t = 1; t < 16; t++) {
            float v  = rvs[tid * 16 + t];
            int   ix = ris[tid * 16 + t];
            if (v < bv || (v == bv && ix < bi)) { bv = v; bi = ix; }
        }
        zsh[tid] = bi;
        out[rowBase + tid] = (float)bi;   // Z as float
    }
    __syncthreads();

    // ---- epilogue: q_with_st = x + (q - x); loss accum in double ----
    double lsum = 0.0;
    const size_t qbase = (size_t)N;
    #pragma unroll
    for (int t = 0; t < (BM * DDIM) / (NT * 4); t++) {   // 16 iters of float4
        int lin4 = tid + t * NT;           // 0..4095
        int row  = lin4 >> 4;
        int dq   = (lin4 & 15) << 2;
        int z    = zsh[row];
        float4 xv = *(const float4*)(x  + (size_t)(rowBase + row) * DDIM + dq);
        float4 qv = *(const float4*)(cb + (size_t)z * DDIM + dq);
        float dx = qv.x - xv.x, dy = qv.y - xv.y, dz = qv.z - xv.z, dw = qv.w - xv.w;
        float4 o = make_float4(xv.x + dx, xv.y + dy, xv.z + dz, xv.w + dw);
        *(float4*)(out + qbase + (size_t)(rowBase + row) * DDIM + dq) = o;
        lsum += (double)dx * dx + (double)dy * dy + (double)dz * dz + (double)dw * dw;
    }
    dred[tid] = lsum;
    __syncthreads();
    #pragma unroll
    for (int s = 128; s > 0; s >>= 1) {
        if (tid < s) dred[tid] += dred[tid + s];
        __syncthreads();
    }
    if (tid == 0) atomicAdd(&g_loss_accum, dred[0]);
}

// ---------------------------------------------------------------------------
extern "C" void kernel_launch(void* const* d_in, const int* in_sizes, int n_in,
                              void* d_out, int out_size) {
    const float* x  = (const float*)d_in[0];
    const float* cb = (const float*)d_in[1];
    float* out = (float*)d_out;

    int N = in_sizes[0] / DDIM;   // 262144
    int K = in_sizes[1] / DDIM;   // 1024

    size_t smemBytes = SMEM_FLOATS * sizeof(float);
    cudaFuncSetAttribute(vq_main_kernel,
                         cudaFuncAttributeMaxDynamicSharedMemorySize,
                         (int)smemBytes);

    zero_kernel<<<1, 1>>>();
    csq_kernel<<<(K + 127) / 128, 128>>>(cb, K);
    vq_main_kernel<<<N / BM, NT, smemBytes>>>(x, cb, out, N, K);
    finalize_kernel<<<1, 1>>>(out, N);
}

// round 7
// speedup vs baseline: 19.1365x; 1.9566x over previous
#include <cuda_runtime.h>
#include <cstdint>

// VQ-VAE quantization: int8 dp4a approximate scoring (rigorous error window)
// + exact fp32 rescore of candidates + fused gather/loss epilogue.
// N=262144, K=1024, D=64. Output fp32: [0,N): Z, [N,N+N*D): q_with_st, +2 losses.

#define NROWS 262144
#define KMAX  1024
#define DDIM  64
#define BM    256          // rows per block (== NT: thread t owns row t)
#define BK    128          // codes per chunk
#define NT    256
#define CAP   24
#define INFF  3.4e38f

__device__ double g_partials[1024];
__device__ float  g_csq[KMAX];
__device__ float  g_scs[KMAX];
__device__ int    g_scM_i;                 // max code scale (float bits)
__device__ int    g_cabM_i;                // max code abs-sum (float bits)
__device__ float  g_sx[NROWS];
__device__ float  g_sumabsq[NROWS];        // sum |sx*xi| per row
__device__ float  g_xsq[NROWS];
__device__ __align__(16) int g_cbq[KMAX * 16];            // packed int8 codes
__device__ __align__(16) int g_xq[(size_t)NROWS * 16];    // packed int8 x

// ---------------------------------------------------------------------------
// signed dp4a via explicit PTX (avoids __dp4a overload ambiguity)
__device__ __forceinline__ int dp4a_s32(int a, int b, int c) {
    int d;
    asm("dp4a.s32.s32 %0, %1, %2, %3;" : "=r"(d) : "r"(a), "r"(b), "r"(c));
    return d;
}

// ---------------------------------------------------------------------------
__global__ void zero_kernel() { g_scM_i = 0; g_cabM_i = 0; }

__global__ void prep_cb_kernel(const float* __restrict__ cb, int K) {
    int k = blockIdx.x * blockDim.x + threadIdx.x;
    if (k >= K) return;
    float ma = 0.f, s = 0.f;
    float cv[DDIM];
    #pragma unroll
    for (int d = 0; d < DDIM; d++) {
        float v = cb[(size_t)k * DDIM + d];
        cv[d] = v;
        s += v * v;
        ma = fmaxf(ma, fabsf(v));
    }
    g_csq[k] = s;
    float sc  = fmaxf(ma, 1e-30f) * (1.0f / 127.0f);
    float inv = 127.0f / fmaxf(ma, 1e-30f);
    g_scs[k] = sc;
    int isum = 0;
    #pragma unroll
    for (int g = 0; g < 16; g++) {
        unsigned pk = 0;
        #pragma unroll
        for (int i = 0; i < 4; i++) {
            int q = __float2int_rn(cv[4 * g + i] * inv);
            isum += abs(q);
            pk |= ((unsigned)(q & 0xFF)) << (8 * i);
        }
        g_cbq[k * 16 + g] = (int)pk;
    }
    float cabs = sc * (float)isum;
    atomicMax(&g_scM_i,  __float_as_int(sc));
    atomicMax(&g_cabM_i, __float_as_int(cabs));
}

// stage rows in smem (stride 68 floats), per-thread row quantization
__global__ void prep_x_kernel(const float* __restrict__ x) {
    extern __shared__ float sm[];                    // [256][68] floats
    int* qb = (int*)(sm + 256 * 68);                 // [256][16]
    int tid = threadIdx.x;
    size_t base = (size_t)blockIdx.x * 256 * DDIM;
    #pragma unroll
    for (int t = 0; t < 16; t++) {
        int lin = tid + t * 256;                     // 0..4095 float4s
        int row = lin >> 4, g = lin & 15;
        float4 v = ((const float4*)(x + base))[lin];
        *(float4*)(sm + row * 68 + g * 4) = v;
    }
    __syncthreads();
    const float* xr = sm + tid * 68;
    float ma = 0.f, xsq = 0.f;
    #pragma unroll
    for (int d = 0; d < DDIM; d++) {
        float v = xr[d];
        ma = fmaxf(ma, fabsf(v));
        xsq += v * v;
    }
    float sx  = fmaxf(ma, 1e-30f) * (1.0f / 127.0f);
    float inv = 127.0f / fmaxf(ma, 1e-30f);
    int isum = 0;
    #pragma unroll
    for (int g = 0; g < 16; g++) {
        unsigned pk = 0;
        #pragma unroll
        for (int i = 0; i < 4; i++) {
            int q = __float2int_rn(xr[4 * g + i] * inv);
            isum += abs(q);
            pk |= ((unsigned)(q & 0xFF)) << (8 * i);
        }
        qb[tid * 16 + g] = (int)pk;
    }
    int grow = blockIdx.x * 256 + tid;
    g_sx[grow]      = sx;
    g_sumabsq[grow] = sx * (float)isum;
    g_xsq[grow]     = xsq;
    __syncthreads();
    #pragma unroll
    for (int t = 0; t < 16; t++) {
        int lin = tid + t * 256;
        g_xq[(size_t)blockIdx.x * 256 * 16 + lin] = qb[lin];
    }
}

__global__ void finalize_kernel(float* __restrict__ out, int N) {
    __shared__ double sd[256];
    int t = threadIdx.x;
    double s = 0.0;
    #pragma unroll
    for (int i = 0; i < 4; i++) s += g_partials[t + i * 256];
    sd[t] = s;
    __syncthreads();
    #pragma unroll
    for (int w = 128; w > 0; w >>= 1) {
        if (t < w) sd[t] += sd[t + w];
        __syncthreads();
    }
    if (t == 0) {
        double mean = sd[0] / ((double)N * (double)DDIM);
        size_t base = (size_t)N + (size_t)N * DDIM;
        out[base]     = (float)mean;
        out[base + 1] = (float)mean;
    }
}

// ---------------------------------------------------------------------------
// main kernel — smem layout (bytes)
#define OFF_A4   0         // 16384  As4: [16 d4][256 rows] i32
#define OFF_B4   16384     // 8192   Bs4: [16 d4][128 codes] i32
#define OFF_CSQ  24576     // 4096
#define OFF_SCS  28672     // 4096
#define OFF_RVS  32768     // 16384  rvs[256 rows][16 tx] float
#define OFF_CAND 49152     // 12288  u16 cand[256][CAP]  (aliased: dred)
#define OFF_CNT  61440     // 1024
#define OFF_ZSH  62464     // 1024
#define OFF_RM   63488     // 1024   rowmin
#define OFF_TAU  64512     // 1024
#define OFF_MSX  65536     // 1024   -2*sx per row
#define SMEM_BYTES 66560

__global__ __launch_bounds__(NT, 1)
void vq_main_kernel(const float* __restrict__ x, const float* __restrict__ cb,
                    float* __restrict__ out, int N, int K) {
    extern __shared__ char smem[];
    int*            As4   = (int*)(smem + OFF_A4);
    int*            Bs4   = (int*)(smem + OFF_B4);
    float*          csq_s = (float*)(smem + OFF_CSQ);
    float*          scs_s = (float*)(smem + OFF_SCS);
    float*          rvs   = (float*)(smem + OFF_RVS);
    unsigned short* cand  = (unsigned short*)(smem + OFF_CAND);
    int*            cnt   = (int*)(smem + OFF_CNT);
    int*            zsh   = (int*)(smem + OFF_ZSH);
    float*          rm_s  = (float*)(smem + OFF_RM);
    float*          tau_s = (float*)(smem + OFF_TAU);
    float*          msx_s = (float*)(smem + OFF_MSX);

    const int tid  = threadIdx.x;
    const int wid  = tid >> 5;
    const int lane = tid & 31;
    const int tx   = tid & 15;   // codes tx + 16*j
    const int ty   = tid >> 4;   // rows ty*16 .. +15
    const int rowBase = blockIdx.x * BM;

    // ---- per-row constants + init ----
    {
        int grow = rowBase + tid;
        float sx = g_sx[grow];
        float scM  = __int_as_float(g_scM_i);
        float cabM = __int_as_float(g_cabM_i);
        // TAU = 2*E_score = 4*E_dot;  E_dot <= sumabsq*scM/2 + cabM*sx/2 + 16*sx*scM
        tau_s[tid] = 2.0f * g_sumabsq[grow] * scM + 2.0f * cabM * sx
                   + 64.0f * sx * scM + 2e-3f;
        msx_s[tid] = -2.0f * sx;
        rm_s[tid]  = INFF;
        cnt[tid]   = 0;
    }
    #pragma unroll
    for (int t = 0; t < 16; t++) rvs[tid + t * NT] = INFF;

    // ---- load quantized A tile transposed: As4[d4][row] ----
    #pragma unroll
    for (int t = 0; t < 4; t++) {
        int lin = tid + t * NT;         // 0..1023 uint4s
        int row = lin >> 2, q = lin & 3;
        int4 v = ((const int4*)g_xq)[(size_t)(rowBase + row) * 4 + q];
        As4[(4 * q + 0) * BM + row] = v.x;
        As4[(4 * q + 1) * BM + row] = v.y;
        As4[(4 * q + 2) * BM + row] = v.z;
        As4[(4 * q + 3) * BM + row] = v.w;
    }
    // ---- csq + scs (all codes) ----
    #pragma unroll
    for (int t = 0; t < KMAX / NT; t++) {
        csq_s[tid + t * NT] = g_csq[tid + t * NT];
        scs_s[tid + t * NT] = g_scs[tid + t * NT];
    }
    __syncthreads();

    // ---- chunk loop ----
    #pragma unroll 1
    for (int cc = 0; cc < KMAX / BK; cc++) {
        const int cbase = cc * BK;

        // load code chunk transposed: Bs4[d4][code]
        #pragma unroll
        for (int t = 0; t < 2; t++) {
            int lin = tid + t * NT;     // 0..511 uint4s
            int code = lin >> 2, q = lin & 3;
            int4 v = ((const int4*)g_cbq)[(size_t)(cbase + code) * 4 + q];
            Bs4[(4 * q + 0) * BK + code] = v.x;
            Bs4[(4 * q + 1) * BK + code] = v.y;
            Bs4[(4 * q + 2) * BK + code] = v.z;
            Bs4[(4 * q + 3) * BK + code] = v.w;
        }
        __syncthreads();

        float csqr[8], scsr[8];
        #pragma unroll
        for (int j = 0; j < 8; j++) {
            csqr[j] = csq_s[cbase + tx + 16 * j];
            scsr[j] = scs_s[cbase + tx + 16 * j];
        }

        // ---- phase A: int8 GEMM, 16 rows x 8 codes per thread ----
        int acc[16][8];
        #pragma unroll
        for (int p = 0; p < 16; p++)
            #pragma unroll
            for (int j = 0; j < 8; j++) acc[p][j] = 0;

        #pragma unroll 4
        for (int d4 = 0; d4 < 16; d4++) {
            const int4* ap4 = (const int4*)(As4 + d4 * BM + ty * 16);
            int4 a0 = ap4[0], a1 = ap4[1], a2 = ap4[2], a3 = ap4[3];
            int av[16] = {a0.x, a0.y, a0.z, a0.w, a1.x, a1.y, a1.z, a1.w,
                          a2.x, a2.y, a2.z, a2.w, a3.x, a3.y, a3.z, a3.w};
            int bv[8];
            #pragma unroll
            for (int j = 0; j < 8; j++) bv[j] = Bs4[d4 * BK + tx + 16 * j];
            #pragma unroll
            for (int p = 0; p < 16; p++)
                #pragma unroll
                for (int j = 0; j < 8; j++)
                    acc[p][j] = dp4a_s32(av[p], bv[j], acc[p][j]);
        }

        // ---- phase B: approx scores -> per-(row,tx) running min ----
        #pragma unroll
        for (int p = 0; p < 16; p++) {
            int row = ty * 16 + p;
            float m = msx_s[row];
            float lm = INFF;
            #pragma unroll
            for (int j = 0; j < 8; j++) {
                float s = fmaf(m * scsr[j], (float)acc[p][j], csqr[j]);
                lm = fminf(lm, s);
            }
            int idx = row * 16 + tx;
            rvs[idx] = fminf(rvs[idx], lm);
        }
        __syncthreads();

        // ---- phase C: per-row min across tx (includes all chunks so far) ----
        {
            float nm = INFF;
            #pragma unroll
            for (int t = 0; t < 16; t++) nm = fminf(nm, rvs[tid * 16 + t]);
            rm_s[tid] = nm;
        }
        __syncthreads();

        // ---- phase D: collect candidates within window ----
        #pragma unroll
        for (int p = 0; p < 16; p++) {
            int row = ty * 16 + p;
            float thr = rm_s[row] + tau_s[row];
            float m = msx_s[row];
            #pragma unroll
            for (int j = 0; j < 8; j++) {
                float s = fmaf(m * scsr[j], (float)acc[p][j], csqr[j]);
                if (s < thr) {
                    int pos = atomicAdd(&cnt[row], 1);
                    if (pos < CAP)
                        cand[row * CAP + pos] = (unsigned short)(cbase + tx + 16 * j);
                }
            }
        }
        __syncthreads();
    }

    // ---- exact fp32 rescore: thread t owns row t ----
    float xr[DDIM];
    {
        const float4* xp = (const float4*)(x + (size_t)(rowBase + tid) * DDIM);
        #pragma unroll
        for (int g = 0; g < 16; g++) {
            float4 v = xp[g];
            xr[4 * g] = v.x; xr[4 * g + 1] = v.y;
            xr[4 * g + 2] = v.z; xr[4 * g + 3] = v.w;
        }
    }
    const float xq = g_xsq[rowBase + tid];
    {
        int c = cnt[tid];
        if (c <= CAP) {
            float best = INFF; int bz = 0;
            #pragma unroll 1
            for (int t = 0; t < c; t++) {
                int idx = cand[tid * CAP + t];
                const float4* cp = (const float4*)(cb + (size_t)idx * DDIM);
                float dot = 0.f;
                #pragma unroll
                for (int g = 0; g < 16; g++) {
                    float4 cv = cp[g];
                    dot = fmaf(xr[4 * g],     cv.x, dot);
                    dot = fmaf(xr[4 * g + 1], cv.y, dot);
                    dot = fmaf(xr[4 * g + 2], cv.z, dot);
                    dot = fmaf(xr[4 * g + 3], cv.w, dot);
                }
                float sc = (xq - 2.0f * dot) + csq_s[idx];
                if (sc < best || (sc == best && idx < bz)) { best = sc; bz = idx; }
            }
            zsh[tid] = bz;
            out[rowBase + tid] = (float)bz;
        }
    }

    // ---- overflow rows: exact exhaustive, warp-parallel (rare) ----
    #pragma unroll 1
    for (int r = wid * 32; r < wid * 32 + 32; r++) {
        if (cnt[r] <= CAP) continue;
        int grow = rowBase + r;
        float yr[DDIM];
        const float4* xp = (const float4*)(x + (size_t)grow * DDIM);
        #pragma unroll
        for (int g = 0; g < 16; g++) {
            float4 v = xp[g];
            yr[4 * g] = v.x; yr[4 * g + 1] = v.y;
            yr[4 * g + 2] = v.z; yr[4 * g + 3] = v.w;
        }
        float yq = g_xsq[grow];
        float best = INFF; int bz = KMAX;
        #pragma unroll 1
        for (int k = lane; k < KMAX; k += 32) {
            const float4* cp = (const float4*)(cb + (size_t)k * DDIM);
            float dot = 0.f;
            #pragma unroll
            for (int g = 0; g < 16; g++) {
                float4 cv = cp[g];
                dot = fmaf(yr[4 * g],     cv.x, dot);
                dot = fmaf(yr[4 * g + 1], cv.y, dot);
                dot = fmaf(yr[4 * g + 2], cv.z, dot);
                dot = fmaf(yr[4 * g + 3], cv.w, dot);
            }
            float sc = (yq - 2.0f * dot) + csq_s[k];
            if (sc < best) { best = sc; bz = k; }
        }
        #pragma unroll
        for (int o = 16; o > 0; o >>= 1) {
            float v  = __shfl_xor_sync(0xffffffffu, best, o);
            int   i2 = __shfl_xor_sync(0xffffffffu, bz, o);
            if (v < best || (v == best && i2 < bz)) { best = v; bz = i2; }
        }
        if (lane == 0) { zsh[r] = bz; out[grow] = (float)bz; }
    }
    __syncthreads();

    // ---- epilogue: q_with_st + loss, per-thread row (xr still in regs) ----
    double lsum = 0.0;
    {
        int z = zsh[tid];
        const float4* cp = (const float4*)(cb + (size_t)z * DDIM);
        float4* op = (float4*)(out + (size_t)N + (size_t)(rowBase + tid) * DDIM);
        #pragma unroll
        for (int g = 0; g < 16; g++) {
            float4 cv = cp[g];
            float dx = cv.x - xr[4 * g];
            float dy = cv.y - xr[4 * g + 1];
            float dz = cv.z - xr[4 * g + 2];
            float dw = cv.w - xr[4 * g + 3];
            op[g] = make_float4(xr[4 * g] + dx, xr[4 * g + 1] + dy,
                                xr[4 * g + 2] + dz, xr[4 * g + 3] + dw);
            lsum += (double)dx * dx + (double)dy * dy
                  + (double)dz * dz + (double)dw * dw;
        }
    }
    double* dred = (double*)(smem + OFF_CAND);   // alias: cand dead
    dred[tid] = lsum;
    __syncthreads();
    #pragma unroll
    for (int s = 128; s > 0; s >>= 1) {
        if (tid < s) dred[tid] += dred[tid + s];
        __syncthreads();
    }
    if (tid == 0) g_partials[blockIdx.x] = dred[0];
}

// ---------------------------------------------------------------------------
extern "C" void kernel_launch(void* const* d_in, const int* in_sizes, int n_in,
                              void* d_out, int out_size) {
    const float* x  = (const float*)d_in[0];
    const float* cb = (const float*)d_in[1];
    float* out = (float*)d_out;

    int N = in_sizes[0] / DDIM;   // 262144
    int K = in_sizes[1] / DDIM;   // 1024

    cudaFuncSetAttribute(vq_main_kernel,
                         cudaFuncAttributeMaxDynamicSharedMemorySize, SMEM_BYTES);
    int prepxSmem = 256 * 68 * 4 + 256 * 16 * 4;
    cudaFuncSetAttribute(prep_x_kernel,
                         cudaFuncAttributeMaxDynamicSharedMemorySize, prepxSmem);

    zero_kernel<<<1, 1>>>();
    prep_cb_kernel<<<(K + 255) / 256, 256>>>(cb, K);
    prep_x_kernel<<<N / 256, 256, prepxSmem>>>(x);
    vq_main_kernel<<<N / BM, NT, SMEM_BYTES>>>(x, cb, out, N, K);
    finalize_kernel<<<1, 256>>>(out, N);
}

// round 9
// speedup vs baseline: 25.2762x; 1.3208x over previous
#include <cuda_runtime.h>
#include <cstdint>

// VQ-VAE quantization: int8 dp4a approximate scoring (rigorous error window)
// + exact fp32 rescore of candidates + fused gather/loss epilogue.
// N=262144, K=1024, D=64. Output fp32: [0,N): Z, [N,N+N*D): q_with_st, +2 losses.
//
// R9 == R8 resubmit (container infra failure): 8x8 per-thread tile (64 accs),
// BM=128, launch_bounds(256,2) -> ~128 regs, ~41KB smem, 2 blocks/SM.

#define NROWS 262144
#define KMAX  1024
#define DDIM  64
#define BM    128          // rows per block
#define BK    128          // codes per chunk
#define NT    256
#define CAP   24
#define INFF  3.4e38f

__device__ double g_partials[2048];
__device__ float  g_csq[KMAX];
__device__ float  g_scs[KMAX];
__device__ int    g_scM_i;                 // max code scale (float bits)
__device__ int    g_cabM_i;                // max code abs-sum (float bits)
__device__ float  g_sx[NROWS];
__device__ float  g_sumabsq[NROWS];        // sum |sx*xi| per row
__device__ float  g_xsq[NROWS];
__device__ __align__(16) int g_cbq[KMAX * 16];            // packed int8 codes
__device__ __align__(16) int g_xq[(size_t)NROWS * 16];    // packed int8 x

// ---------------------------------------------------------------------------
__device__ __forceinline__ int dp4a_s32(int a, int b, int c) {
    int d;
    asm("dp4a.s32.s32 %0, %1, %2, %3;" : "=r"(d) : "r"(a), "r"(b), "r"(c));
    return d;
}

// ---------------------------------------------------------------------------
__global__ void zero_kernel() { g_scM_i = 0; g_cabM_i = 0; }

__global__ void prep_cb_kernel(const float* __restrict__ cb, int K) {
    int k = blockIdx.x * blockDim.x + threadIdx.x;
    if (k >= K) return;
    float ma = 0.f, s = 0.f;
    float cv[DDIM];
    #pragma unroll
    for (int d = 0; d < DDIM; d++) {
        float v = cb[(size_t)k * DDIM + d];
        cv[d] = v;
        s += v * v;
        ma = fmaxf(ma, fabsf(v));
    }
    g_csq[k] = s;
    float sc  = fmaxf(ma, 1e-30f) * (1.0f / 127.0f);
    float inv = 127.0f / fmaxf(ma, 1e-30f);
    g_scs[k] = sc;
    int isum = 0;
    #pragma unroll
    for (int g = 0; g < 16; g++) {
        unsigned pk = 0;
        #pragma unroll
        for (int i = 0; i < 4; i++) {
            int q = __float2int_rn(cv[4 * g + i] * inv);
            isum += abs(q);
            pk |= ((unsigned)(q & 0xFF)) << (8 * i);
        }
        g_cbq[k * 16 + g] = (int)pk;
    }
    float cabs = sc * (float)isum;
    atomicMax(&g_scM_i,  __float_as_int(sc));
    atomicMax(&g_cabM_i, __float_as_int(cabs));
}

__global__ void prep_x_kernel(const float* __restrict__ x) {
    extern __shared__ float sm[];                    // [256][68] floats
    int* qb = (int*)(sm + 256 * 68);                 // [256][16]
    int tid = threadIdx.x;
    size_t base = (size_t)blockIdx.x * 256 * DDIM;
    #pragma unroll
    for (int t = 0; t < 16; t++) {
        int lin = tid + t * 256;                     // 0..4095 float4s
        int row = lin >> 4, g = lin & 15;
        float4 v = ((const float4*)(x + base))[lin];
        *(float4*)(sm + row * 68 + g * 4) = v;
    }
    __syncthreads();
    const float* xr = sm + tid * 68;
    float ma = 0.f, xsq = 0.f;
    #pragma unroll
    for (int d = 0; d < DDIM; d++) {
        float v = xr[d];
        ma = fmaxf(ma, fabsf(v));
        xsq += v * v;
    }
    float sx  = fmaxf(ma, 1e-30f) * (1.0f / 127.0f);
    float inv = 127.0f / fmaxf(ma, 1e-30f);
    int isum = 0;
    #pragma unroll
    for (int g = 0; g < 16; g++) {
        unsigned pk = 0;
        #pragma unroll
        for (int i = 0; i < 4; i++) {
            int q = __float2int_rn(xr[4 * g + i] * inv);
            isum += abs(q);
            pk |= ((unsigned)(q & 0xFF)) << (8 * i);
        }
        qb[tid * 16 + g] = (int)pk;
    }
    int grow = blockIdx.x * 256 + tid;
    g_sx[grow]      = sx;
    g_sumabsq[grow] = sx * (float)isum;
    g_xsq[grow]     = xsq;
    __syncthreads();
    #pragma unroll
    for (int t = 0; t < 16; t++) {
        int lin = tid + t * 256;
        g_xq[(size_t)blockIdx.x * 256 * 16 + lin] = qb[lin];
    }
}

__global__ void finalize_kernel(float* __restrict__ out, int N) {
    __shared__ double sd[256];
    int t = threadIdx.x;
    double s = 0.0;
    #pragma unroll
    for (int i = 0; i < 8; i++) s += g_partials[t + i * 256];
    sd[t] = s;
    __syncthreads();
    #pragma unroll
    for (int w = 128; w > 0; w >>= 1) {
        if (t < w) sd[t] += sd[t + w];
        __syncthreads();
    }
    if (t == 0) {
        double mean = sd[0] / ((double)N * (double)DDIM);
        size_t base = (size_t)N + (size_t)N * DDIM;
        out[base]     = (float)mean;
        out[base + 1] = (float)mean;
    }
}

// ---------------------------------------------------------------------------
// main kernel — smem layout (bytes)
#define OFF_A4   0         // 8192   As4: [16 d4][128 rows] i32
#define OFF_B4   8192      // 8192   Bs4: [16 d4][128 codes] i32
#define OFF_CSQ  16384     // 4096
#define OFF_SCS  20480     // 4096
#define OFF_RVS  24576     // 8192   rvs[128 rows][16 tx] float
#define OFF_CAND 32768     // 6144   u16 cand[128][CAP]  (aliased: dred)
#define OFF_CNT  38912     // 512
#define OFF_ZSH  39424     // 512
#define OFF_RM   39936     // 512    rowmin
#define OFF_TAU  40448     // 512
#define OFF_MSX  40960     // 512    -2*sx per row
#define SMEM_BYTES 41472

__global__ __launch_bounds__(NT, 2)
void vq_main_kernel(const float* __restrict__ x, const float* __restrict__ cb,
                    float* __restrict__ out, int N, int K) {
    extern __shared__ char smem[];
    int*            As4   = (int*)(smem + OFF_A4);
    int*            Bs4   = (int*)(smem + OFF_B4);
    float*          csq_s = (float*)(smem + OFF_CSQ);
    float*          scs_s = (float*)(smem + OFF_SCS);
    float*          rvs   = (float*)(smem + OFF_RVS);
    unsigned short* cand  = (unsigned short*)(smem + OFF_CAND);
    int*            cnt   = (int*)(smem + OFF_CNT);
    int*            zsh   = (int*)(smem + OFF_ZSH);
    float*          rm_s  = (float*)(smem + OFF_RM);
    float*          tau_s = (float*)(smem + OFF_TAU);
    float*          msx_s = (float*)(smem + OFF_MSX);

    const int tid  = threadIdx.x;
    const int wid  = tid >> 5;
    const int lane = tid & 31;
    const int tx   = tid & 15;   // codes tx + 16*j
    const int ty   = tid >> 4;   // rows ty*8 .. ty*8+7
    const int rowBase = blockIdx.x * BM;

    // ---- per-row constants + init (threads 0..127 own one row each) ----
    if (tid < BM) {
        int grow = rowBase + tid;
        float sx = g_sx[grow];
        float scM  = __int_as_float(g_scM_i);
        float cabM = __int_as_float(g_cabM_i);
        // TAU = 2*E_score = 4*E_dot;  E_dot <= sumabsq*scM/2 + cabM*sx/2 + 16*sx*scM
        tau_s[tid] = 2.0f * g_sumabsq[grow] * scM + 2.0f * cabM * sx
                   + 64.0f * sx * scM + 2e-3f;
        msx_s[tid] = -2.0f * sx;
        rm_s[tid]  = INFF;
        cnt[tid]   = 0;
    }
    #pragma unroll
    for (int t = 0; t < (BM * 16) / NT; t++) rvs[tid + t * NT] = INFF;

    // ---- load quantized A tile transposed: As4[d4][row] ----
    #pragma unroll
    for (int t = 0; t < 2; t++) {
        int lin = tid + t * NT;         // 0..511 int4s
        int row = lin >> 2, q = lin & 3;
        int4 v = ((const int4*)g_xq)[(size_t)(rowBase + row) * 4 + q];
        As4[(4 * q + 0) * BM + row] = v.x;
        As4[(4 * q + 1) * BM + row] = v.y;
        As4[(4 * q + 2) * BM + row] = v.z;
        As4[(4 * q + 3) * BM + row] = v.w;
    }
    // ---- csq + scs (all codes) ----
    #pragma unroll
    for (int t = 0; t < KMAX / NT; t++) {
        csq_s[tid + t * NT] = g_csq[tid + t * NT];
        scs_s[tid + t * NT] = g_scs[tid + t * NT];
    }
    __syncthreads();

    // ---- chunk loop ----
    #pragma unroll 1
    for (int cc = 0; cc < KMAX / BK; cc++) {
        const int cbase = cc * BK;

        // load code chunk transposed: Bs4[d4][code]
        #pragma unroll
        for (int t = 0; t < 2; t++) {
            int l2 = tid + t * NT;      // 0..511 int4s
            int code = l2 >> 2, q = l2 & 3;
            int4 v = ((const int4*)g_cbq)[(size_t)(cbase + code) * 4 + q];
            Bs4[(4 * q + 0) * BK + code] = v.x;
            Bs4[(4 * q + 1) * BK + code] = v.y;
            Bs4[(4 * q + 2) * BK + code] = v.z;
            Bs4[(4 * q + 3) * BK + code] = v.w;
        }
        __syncthreads();

        float csqr[8], scsr[8];
        #pragma unroll
        for (int j = 0; j < 8; j++) {
            csqr[j] = csq_s[cbase + tx + 16 * j];
            scsr[j] = scs_s[cbase + tx + 16 * j];
        }

        // ---- phase A: int8 GEMM, 8 rows x 8 codes per thread ----
        int acc[8][8];
        #pragma unroll
        for (int p = 0; p < 8; p++)
            #pragma unroll
            for (int j = 0; j < 8; j++) acc[p][j] = 0;

        #pragma unroll 4
        for (int d4 = 0; d4 < 16; d4++) {
            const int4* ap4 = (const int4*)(As4 + d4 * BM + ty * 8);
            int4 a0 = ap4[0], a1 = ap4[1];
            int av[8] = {a0.x, a0.y, a0.z, a0.w, a1.x, a1.y, a1.z, a1.w};
            int bv[8];
            #pragma unroll
            for (int j = 0; j < 8; j++) bv[j] = Bs4[d4 * BK + tx + 16 * j];
            #pragma unroll
            for (int p = 0; p < 8; p++)
                #pragma unroll
                for (int j = 0; j < 8; j++)
                    acc[p][j] = dp4a_s32(av[p], bv[j], acc[p][j]);
        }

        // ---- phase B: approx scores -> per-(row,tx) running min ----
        #pragma unroll
        for (int p = 0; p < 8; p++) {
            int row = ty * 8 + p;
            float m = msx_s[row];
            float lm = INFF;
            #pragma unroll
            for (int j = 0; j < 8; j++) {
                float s = fmaf(m * scsr[j], (float)acc[p][j], csqr[j]);
                lm = fminf(lm, s);
            }
            int idx = row * 16 + tx;
            rvs[idx] = fminf(rvs[idx], lm);
        }
        __syncthreads();

        // ---- phase C: per-row min across tx (upper-bounds final min) ----
        if (tid < BM) {
            float nm = INFF;
            #pragma unroll
            for (int t = 0; t < 16; t++) nm = fminf(nm, rvs[tid * 16 + t]);
            rm_s[tid] = nm;
        }
        __syncthreads();

        // ---- phase D: collect candidates within window ----
        #pragma unroll
        for (int p = 0; p < 8; p++) {
            int row = ty * 8 + p;
            float thr = rm_s[row] + tau_s[row];
            float m = msx_s[row];
            #pragma unroll
            for (int j = 0; j < 8; j++) {
                float s = fmaf(m * scsr[j], (float)acc[p][j], csqr[j]);
                if (s < thr) {
                    int pos = atomicAdd(&cnt[row], 1);
                    if (pos < CAP)
                        cand[row * CAP + pos] = (unsigned short)(cbase + tx + 16 * j);
                }
            }
        }
        __syncthreads();
    }

    // ---- exact fp32 rescore: threads 0..127 own one row each ----
    if (tid < BM) {
        int c = cnt[tid];
        if (c <= CAP) {
            float xr[DDIM];
            const float4* xp = (const float4*)(x + (size_t)(rowBase + tid) * DDIM);
            #pragma unroll
            for (int g = 0; g < 16; g++) {
                float4 v = xp[g];
                xr[4 * g] = v.x; xr[4 * g + 1] = v.y;
                xr[4 * g + 2] = v.z; xr[4 * g + 3] = v.w;
            }
            float xq = g_xsq[rowBase + tid];
            float best = INFF; int bz = 0;
            #pragma unroll 1
            for (int t = 0; t < c; t++) {
                int idx = cand[tid * CAP + t];
                const float4* cp = (const float4*)(cb + (size_t)idx * DDIM);
                float dot = 0.f;
                #pragma unroll
                for (int g = 0; g < 16; g++) {
                    float4 cv = cp[g];
                    dot = fmaf(xr[4 * g],     cv.x, dot);
                    dot = fmaf(xr[4 * g + 1], cv.y, dot);
                    dot = fmaf(xr[4 * g + 2], cv.z, dot);
                    dot = fmaf(xr[4 * g + 3], cv.w, dot);
                }
                float sc = (xq - 2.0f * dot) + csq_s[idx];
                if (sc < best || (sc == best && idx < bz)) { best = sc; bz = idx; }
            }
            zsh[tid] = bz;
            out[rowBase + tid] = (float)bz;
        }
    }

    // ---- overflow rows: exact exhaustive, warp-parallel (rare) ----
    #pragma unroll 1
    for (int r = wid * 16; r < wid * 16 + 16; r++) {
        if (cnt[r] <= CAP) continue;
        int grow = rowBase + r;
        float yr[DDIM];
        const float4* xp = (const float4*)(x + (size_t)grow * DDIM);
        #pragma unroll
        for (int g = 0; g < 16; g++) {
            float4 v = xp[g];
            yr[4 * g] = v.x; yr[4 * g + 1] = v.y;
            yr[4 * g + 2] = v.z; yr[4 * g + 3] = v.w;
        }
        float yq = g_xsq[grow];
        float best = INFF; int bz = KMAX;
        #pragma unroll 1
        for (int k = lane; k < KMAX; k += 32) {
            const float4* cp = (const float4*)(cb + (size_t)k * DDIM);
            float dot = 0.f;
            #pragma unroll
            for (int g = 0; g < 16; g++) {
                float4 cv = cp[g];
                dot = fmaf(yr[4 * g],     cv.x, dot);
                dot = fmaf(yr[4 * g + 1], cv.y, dot);
                dot = fmaf(yr[4 * g + 2], cv.z, dot);
                dot = fmaf(yr[4 * g + 3], cv.w, dot);
            }
            float sc = (yq - 2.0f * dot) + csq_s[k];
            if (sc < best) { best = sc; bz = k; }
        }
        #pragma unroll
        for (int o = 16; o > 0; o >>= 1) {
            float v  = __shfl_xor_sync(0xffffffffu, best, o);
            int   i2 = __shfl_xor_sync(0xffffffffu, bz, o);
            if (v < best || (v == best && i2 < bz)) { best = v; bz = i2; }
        }
        if (lane == 0) { zsh[r] = bz; out[grow] = (float)bz; }
    }
    __syncthreads();

    // ---- epilogue: q_with_st + loss (coalesced; 128 rows x 16 f4) ----
    double lsum = 0.0;
    const size_t qbase = (size_t)N;
    #pragma unroll
    for (int t = 0; t < (BM * 16) / NT; t++) {   // 8 iters
        int lin = tid + t * NT;                  // 0..2047 f4s
        int row = lin >> 4;
        int g   = lin & 15;
        int z   = zsh[row];
        float4 xv = ((const float4*)(x  + (size_t)(rowBase + row) * DDIM))[g];
        float4 cv = ((const float4*)(cb + (size_t)z * DDIM))[g];
        float dx = cv.x - xv.x, dy = cv.y - xv.y, dz = cv.z - xv.z, dw = cv.w - xv.w;
        ((float4*)(out + qbase + (size_t)(rowBase + row) * DDIM))[g] =
            make_float4(xv.x + dx, xv.y + dy, xv.z + dz, xv.w + dw);
        lsum += (double)dx * dx + (double)dy * dy + (double)dz * dz + (double)dw * dw;
    }
    double* dred = (double*)(smem + OFF_CAND);   // alias: cand dead
    dred[tid] = lsum;
    __syncthreads();
    #pragma unroll
    for (int s = 128; s > 0; s >>= 1) {
        if (tid < s) dred[tid] += dred[tid + s];
        __syncthreads();
    }
    if (tid == 0) g_partials[blockIdx.x] = dred[0];
}

// ---------------------------------------------------------------------------
extern "C" void kernel_launch(void* const* d_in, const int* in_sizes, int n_in,
                              void* d_out, int out_size) {
    const float* x  = (const float*)d_in[0];
    const float* cb = (const float*)d_in[1];
    float* out = (float*)d_out;

    int N = in_sizes[0] / DDIM;   // 262144
    int K = in_sizes[1] / DDIM;   // 1024

    cudaFuncSetAttribute(vq_main_kernel,
                         cudaFuncAttributeMaxDynamicSharedMemorySize, SMEM_BYTES);
    int prepxSmem = 256 * 68 * 4 + 256 * 16 * 4;
    cudaFuncSetAttribute(prep_x_kernel,
                         cudaFuncAttributeMaxDynamicSharedMemorySize, prepxSmem);

    zero_kernel<<<1, 1>>>();
    prep_cb_kernel<<<(K + 255) / 256, 256>>>(cb, K);
    prep_x_kernel<<<N / 256, 256, prepxSmem>>>(x);
    vq_main_kernel<<<N / BM, NT, SMEM_BYTES>>>(x, cb, out, N, K);
    finalize_kernel<<<1, 256>>>(out, N);
}

// round 10
// speedup vs baseline: 27.0576x; 1.0705x over previous
#include <cuda_runtime.h>
#include <cstdint>

// VQ-VAE quantization: int8 dp4a approximate scoring (rigorous error window)
// + exact fp32 rescore of candidates + fused gather/loss epilogue.
// N=262144, K=1024, D=64. Output fp32: [0,N): Z, [N,N+N*D): q_with_st, +2 losses.
//
// R10: 8x8 tile, BM=128, 2 blocks/SM. New vs R9:
//  - per-row running min kept in REGISTERS via half-warp shfl butterfly
//    (each row's 16 tx lanes are one half-warp; row ownership never crosses warps)
//  - cp.async double-buffered B chunks (codebook stored chunk-transposed)
//  - scores computed once, stored over dp4a accumulators
//  - 1 syncthreads per chunk (was 4)

#define NROWS 262144
#define KMAX  1024
#define DDIM  64
#define BM    128
#define BK    128
#define NT    256
#define CAP   24
#define INFF  3.4e38f

__device__ double g_partials[2048];
__device__ float  g_csq[KMAX];
__device__ float  g_scs[KMAX];
__device__ int    g_scM_i;
__device__ int    g_cabM_i;
__device__ float  g_sx[NROWS];
__device__ float  g_sumabsq[NROWS];
__device__ float  g_xsq[NROWS];
// codebook packed int8, CHUNK-TRANSPOSED: g_cbqT[chunk][d4][code] (chunk=128 codes)
__device__ __align__(16) int g_cbqT[KMAX * 16];
__device__ __align__(16) int g_xq[(size_t)NROWS * 16];

// ---------------------------------------------------------------------------
__device__ __forceinline__ int dp4a_s32(int a, int b, int c) {
    int d;
    asm("dp4a.s32.s32 %0, %1, %2, %3;" : "=r"(d) : "r"(a), "r"(b), "r"(c));
    return d;
}
__device__ __forceinline__ uint32_t smem_u32(const void* p) {
    uint32_t a;
    asm("{ .reg .u64 t; cvta.to.shared.u64 t, %1; cvt.u32.u64 %0, t; }" : "=r"(a) : "l"(p));
    return a;
}
__device__ __forceinline__ void cp_async16(uint32_t dst, const void* src) {
    asm volatile("cp.async.cg.shared.global [%0], [%1], 16;" :: "r"(dst), "l"(src));
}
#define CP_COMMIT() asm volatile("cp.async.commit_group;")
#define CP_WAIT0()  asm volatile("cp.async.wait_group 0;")

// ---------------------------------------------------------------------------
__global__ void zero_kernel() { g_scM_i = 0; g_cabM_i = 0; }

__global__ void prep_cb_kernel(const float* __restrict__ cb, int K) {
    int k = blockIdx.x * blockDim.x + threadIdx.x;
    if (k >= K) return;
    float ma = 0.f, s = 0.f;
    float cv[DDIM];
    #pragma unroll
    for (int d = 0; d < DDIM; d++) {
        float v = cb[(size_t)k * DDIM + d];
        cv[d] = v;
        s += v * v;
        ma = fmaxf(ma, fabsf(v));
    }
    g_csq[k] = s;
    float sc  = fmaxf(ma, 1e-30f) * (1.0f / 127.0f);
    float inv = 127.0f / fmaxf(ma, 1e-30f);
    g_scs[k] = sc;
    int isum = 0;
    int chunk = k >> 7, code = k & 127;
    #pragma unroll
    for (int g = 0; g < 16; g++) {
        unsigned pk = 0;
        #pragma unroll
        for (int i = 0; i < 4; i++) {
            int q = __float2int_rn(cv[4 * g + i] * inv);
            isum += abs(q);
            pk |= ((unsigned)(q & 0xFF)) << (8 * i);
        }
        g_cbqT[chunk * 2048 + g * 128 + code] = (int)pk;   // [chunk][d4][code]
    }
    float cabs = sc * (float)isum;
    atomicMax(&g_scM_i,  __float_as_int(sc));
    atomicMax(&g_cabM_i, __float_as_int(cabs));
}

__global__ void prep_x_kernel(const float* __restrict__ x) {
    extern __shared__ float sm[];                    // [256][68]
    int* qb = (int*)(sm + 256 * 68);
    int tid = threadIdx.x;
    size_t base = (size_t)blockIdx.x * 256 * DDIM;
    #pragma unroll
    for (int t = 0; t < 16; t++) {
        int lin = tid + t * 256;
        int row = lin >> 4, g = lin & 15;
        float4 v = ((const float4*)(x + base))[lin];
        *(float4*)(sm + row * 68 + g * 4) = v;
    }
    __syncthreads();
    const float* xr = sm + tid * 68;
    float ma = 0.f, xsq = 0.f;
    #pragma unroll
    for (int d = 0; d < DDIM; d++) {
        float v = xr[d];
        ma = fmaxf(ma, fabsf(v));
        xsq += v * v;
    }
    float sx  = fmaxf(ma, 1e-30f) * (1.0f / 127.0f);
    float inv = 127.0f / fmaxf(ma, 1e-30f);
    int isum = 0;
    #pragma unroll
    for (int g = 0; g < 16; g++) {
        unsigned pk = 0;
        #pragma unroll
        for (int i = 0; i < 4; i++) {
            int q = __float2int_rn(xr[4 * g + i] * inv);
            isum += abs(q);
            pk |= ((unsigned)(q & 0xFF)) << (8 * i);
        }
        qb[tid * 16 + g] = (int)pk;
    }
    int grow = blockIdx.x * 256 + tid;
    g_sx[grow]      = sx;
    g_sumabsq[grow] = sx * (float)isum;
    g_xsq[grow]     = xsq;
    __syncthreads();
    #pragma unroll
    for (int t = 0; t < 16; t++) {
        int lin = tid + t * 256;
        g_xq[(size_t)blockIdx.x * 256 * 16 + lin] = qb[lin];
    }
}

__global__ void finalize_kernel(float* __restrict__ out, int N) {
    __shared__ double sd[256];
    int t = threadIdx.x;
    double s = 0.0;
    #pragma unroll
    for (int i = 0; i < 8; i++) s += g_partials[t + i * 256];
    sd[t] = s;
    __syncthreads();
    #pragma unroll
    for (int w = 128; w > 0; w >>= 1) {
        if (t < w) sd[t] += sd[t + w];
        __syncthreads();
    }
    if (t == 0) {
        double mean = sd[0] / ((double)N * (double)DDIM);
        size_t base = (size_t)N + (size_t)N * DDIM;
        out[base]     = (float)mean;
        out[base + 1] = (float)mean;
    }
}

// ---------------------------------------------------------------------------
// smem layout (bytes)
#define OFF_A4   0         // 8192  As4: [16 d4][128 rows] i32
#define OFF_B0   8192      // 8192  B chunk buf 0: [16 d4][128 codes] i32
#define OFF_B1   16384     // 8192  buf 1
#define OFF_CSQ  24576     // 4096
#define OFF_SCS  28672     // 4096
#define OFF_CAND 32768     // 6144  u16 cand[128][CAP] (aliased: dred)
#define OFF_CNT  38912     // 512
#define OFF_ZSH  39424     // 512
#define OFF_TAU  39936     // 512
#define OFF_MSX  40448     // 512
#define SMEM_BYTES 40960

__global__ __launch_bounds__(NT, 2)
void vq_main_kernel(const float* __restrict__ x, const float* __restrict__ cb,
                    float* __restrict__ out, int N, int K) {
    extern __shared__ char smem[];
    const uint32_t  smb  = smem_u32(smem);
    int*            As4   = (int*)(smem + OFF_A4);
    float*          csq_s = (float*)(smem + OFF_CSQ);
    float*          scs_s = (float*)(smem + OFF_SCS);
    unsigned short* cand  = (unsigned short*)(smem + OFF_CAND);
    int*            cnt   = (int*)(smem + OFF_CNT);
    int*            zsh   = (int*)(smem + OFF_ZSH);
    float*          tau_s = (float*)(smem + OFF_TAU);
    float*          msx_s = (float*)(smem + OFF_MSX);

    const int tid  = threadIdx.x;
    const int wid  = tid >> 5;
    const int lane = tid & 31;
    const int tx   = tid & 15;
    const int ty   = tid >> 4;     // rows ty*8 .. ty*8+7 (fixed half-warp per row!)
    const int rowBase = blockIdx.x * BM;

    if (tid < BM) {
        int grow = rowBase + tid;
        float sx = g_sx[grow];
        float scM  = __int_as_float(g_scM_i);
        float cabM = __int_as_float(g_cabM_i);
        // TAU = 2*E_score = 4*E_dot; E_dot <= sumabsq*scM/2 + cabM*sx/2 + 16*sx*scM
        tau_s[tid] = 2.0f * g_sumabsq[grow] * scM + 2.0f * cabM * sx
                   + 64.0f * sx * scM + 2e-3f;
        msx_s[tid] = -2.0f * sx;
        cnt[tid]   = 0;
    }

    // A tile transposed: As4[d4][row]
    #pragma unroll
    for (int t = 0; t < 2; t++) {
        int lin = tid + t * NT;
        int row = lin >> 2, q = lin & 3;
        int4 v = ((const int4*)g_xq)[(size_t)(rowBase + row) * 4 + q];
        As4[(4 * q + 0) * BM + row] = v.x;
        As4[(4 * q + 1) * BM + row] = v.y;
        As4[(4 * q + 2) * BM + row] = v.z;
        As4[(4 * q + 3) * BM + row] = v.w;
    }
    #pragma unroll
    for (int t = 0; t < KMAX / NT; t++) {
        csq_s[tid + t * NT] = g_csq[tid + t * NT];
        scs_s[tid + t * NT] = g_scs[tid + t * NT];
    }

    // prefetch chunk 0 -> buf0 (contiguous 8KB: g_cbqT is chunk-major)
    {
        const char* src = (const char*)g_cbqT + (size_t)tid * 16;
        cp_async16(smb + OFF_B0 + tid * 16,        src);
        cp_async16(smb + OFF_B0 + (tid + NT) * 16, src + NT * 16);
        CP_COMMIT();
    }

    float rmreg[8];           // running per-row approx min (register-resident)
    #pragma unroll
    for (int p = 0; p < 8; p++) rmreg[p] = INFF;

    CP_WAIT0();
    __syncthreads();          // A/csq/tau + chunk0 visible block-wide

    #pragma unroll 1
    for (int cc = 0; cc < KMAX / BK; cc++) {
        const int cbase = cc * BK;
        int* bufp = (int*)(smem + ((cc & 1) ? OFF_B1 : OFF_B0));

        // prefetch next chunk into the other buffer (overlaps compute)
        if (cc < KMAX / BK - 1) {
            uint32_t dst = smb + (((cc + 1) & 1) ? OFF_B1 : OFF_B0);
            const char* src = (const char*)g_cbqT + (size_t)(cc + 1) * 8192
                            + (size_t)tid * 16;
            cp_async16(dst + tid * 16,        src);
            cp_async16(dst + (tid + NT) * 16, src + NT * 16);
            CP_COMMIT();
        }

        float csqr[8], scsr[8];
        #pragma unroll
        for (int j = 0; j < 8; j++) {
            csqr[j] = csq_s[cbase + tx + 16 * j];
            scsr[j] = scs_s[cbase + tx + 16 * j];
        }

        // ---- phase A: dp4a GEMM 8 rows x 8 codes ----
        int acc[8][8];
        #pragma unroll
        for (int p = 0; p < 8; p++)
            #pragma unroll
            for (int j = 0; j < 8; j++) acc[p][j] = 0;

        #pragma unroll 4
        for (int d4 = 0; d4 < 16; d4++) {
            const int4* ap4 = (const int4*)(As4 + d4 * BM + ty * 8);
            int4 a0 = ap4[0], a1 = ap4[1];
            int av[8] = {a0.x, a0.y, a0.z, a0.w, a1.x, a1.y, a1.z, a1.w};
            int bv[8];
            #pragma unroll
            for (int j = 0; j < 8; j++) bv[j] = bufp[d4 * BK + tx + 16 * j];
            #pragma unroll
            for (int p = 0; p < 8; p++)
                #pragma unroll
                for (int j = 0; j < 8; j++)
                    acc[p][j] = dp4a_s32(av[p], bv[j], acc[p][j]);
        }

        // ---- phase B: scores (stored over acc) + half-warp row-min reduce ----
        // Row r's 16 tx lanes form one half-warp: shfl butterfly (xor 1,2,4,8)
        // yields the complete chunk row-min; rmreg accumulates across chunks.
        // TAU guarantee: any rm >= final approx rowmin F suffices:
        //   s_approx(k*) <= exact_min + E <= (F + E) + E <= rm + 2E < rm + TAU.
        #pragma unroll
        for (int p = 0; p < 8; p++) {
            int row = ty * 8 + p;
            float m = msx_s[row];
            float lm = INFF;
            #pragma unroll
            for (int j = 0; j < 8; j++) {
                float s = fmaf(m * scsr[j], (float)acc[p][j], csqr[j]);
                acc[p][j] = __float_as_int(s);
                lm = fminf(lm, s);
            }
            #pragma unroll
            for (int o = 1; o <= 8; o <<= 1)
                lm = fminf(lm, __shfl_xor_sync(0xffffffffu, lm, o));
            rmreg[p] = fminf(rmreg[p], lm);
        }

        // ---- phase D: collect candidates within window ----
        #pragma unroll
        for (int p = 0; p < 8; p++) {
            int row = ty * 8 + p;
            float thr = rmreg[p] + tau_s[row];
            #pragma unroll
            for (int j = 0; j < 8; j++) {
                float s = __int_as_float(acc[p][j]);
                if (s < thr) {
                    int pos = atomicAdd(&cnt[row], 1);
                    if (pos < CAP)
                        cand[row * CAP + pos] = (unsigned short)(cbase + tx + 16 * j);
                }
            }
        }

        // buffer handoff: own copies done + all threads past this chunk's reads
        CP_WAIT0();
        __syncthreads();
    }

    // ---- exact fp32 rescore: threads 0..127 own one row each ----
    if (tid < BM) {
        int c = cnt[tid];
        if (c <= CAP) {
            float xr[DDIM];
            const float4* xp = (const float4*)(x + (size_t)(rowBase + tid) * DDIM);
            #pragma unroll
            for (int g = 0; g < 16; g++) {
                float4 v = xp[g];
                xr[4 * g] = v.x; xr[4 * g + 1] = v.y;
                xr[4 * g + 2] = v.z; xr[4 * g + 3] = v.w;
            }
            float xq = g_xsq[rowBase + tid];
            float best = INFF; int bz = 0;
            #pragma unroll 1
            for (int t = 0; t < c; t++) {
                int idx = cand[tid * CAP + t];
                const float4* cp = (const float4*)(cb + (size_t)idx * DDIM);
                float dot = 0.f;
                #pragma unroll
                for (int g = 0; g < 16; g++) {
                    float4 cv = cp[g];
                    dot = fmaf(xr[4 * g],     cv.x, dot);
                    dot = fmaf(xr[4 * g + 1], cv.y, dot);
                    dot = fmaf(xr[4 * g + 2], cv.z, dot);
                    dot = fmaf(xr[4 * g + 3], cv.w, dot);
                }
                float sc = (xq - 2.0f * dot) + csq_s[idx];
                if (sc < best || (sc == best && idx < bz)) { best = sc; bz = idx; }
            }
            zsh[tid] = bz;
            out[rowBase + tid] = (float)bz;
        }
    }

    // ---- overflow rows: exact exhaustive, warp-parallel (rare) ----
    #pragma unroll 1
    for (int r = wid * 16; r < wid * 16 + 16; r++) {
        if (cnt[r] <= CAP) continue;
        int grow = rowBase + r;
        float yr[DDIM];
        const float4* xp = (const float4*)(x + (size_t)grow * DDIM);
        #pragma unroll
        for (int g = 0; g < 16; g++) {
            float4 v = xp[g];
            yr[4 * g] = v.x; yr[4 * g + 1] = v.y;
            yr[4 * g + 2] = v.z; yr[4 * g + 3] = v.w;
        }
        float yq = g_xsq[grow];
        float best = INFF; int bz = KMAX;
        #pragma unroll 1
        for (int k = lane; k < KMAX; k += 32) {
            const float4* cp = (const float4*)(cb + (size_t)k * DDIM);
            float dot = 0.f;
            #pragma unroll
            for (int g = 0; g < 16; g++) {
                float4 cv = cp[g];
                dot = fmaf(yr[4 * g],     cv.x, dot);
                dot = fmaf(yr[4 * g + 1], cv.y, dot);
                dot = fmaf(yr[4 * g + 2], cv.z, dot);
                dot = fmaf(yr[4 * g + 3], cv.w, dot);
            }
            float sc = (yq - 2.0f * dot) + csq_s[k];
            if (sc < best) { best = sc; bz = k; }
        }
        #pragma unroll
        for (int o = 16; o > 0; o >>= 1) {
            float v  = __shfl_xor_sync(0xffffffffu, best, o);
            int   i2 = __shfl_xor_sync(0xffffffffu, bz, o);
            if (v < best || (v == best && i2 < bz)) { best = v; bz = i2; }
        }
        if (lane == 0) { zsh[r] = bz; out[grow] = (float)bz; }
    }
    __syncthreads();

    // ---- epilogue: q_with_st + loss (coalesced) ----
    double lsum = 0.0;
    const size_t qbase = (size_t)N;
    #pragma unroll
    for (int t = 0; t < (BM * 16) / NT; t++) {
        int lin = tid + t * NT;
        int row = lin >> 4;
        int g   = lin & 15;
        int z   = zsh[row];
        float4 xv = ((const float4*)(x  + (size_t)(rowBase + row) * DDIM))[g];
        float4 cv = ((const float4*)(cb + (size_t)z * DDIM))[g];
        float dx = cv.x - xv.x, dy = cv.y - xv.y, dz = cv.z - xv.z, dw = cv.w - xv.w;
        ((float4*)(out + qbase + (size_t)(rowBase + row) * DDIM))[g] =
            make_float4(xv.x + dx, xv.y + dy, xv.z + dz, xv.w + dw);
        lsum += (double)dx * dx + (double)dy * dy + (double)dz * dz + (double)dw * dw;
    }
    double* dred = (double*)(smem + OFF_CAND);   // alias: cand dead
    dred[tid] = lsum;
    __syncthreads();
    #pragma unroll
    for (int s = 128; s > 0; s >>= 1) {
        if (tid < s) dred[tid] += dred[tid + s];
        __syncthreads();
    }
    if (tid == 0) g_partials[blockIdx.x] = dred[0];
}

// ---------------------------------------------------------------------------
extern "C" void kernel_launch(void* const* d_in, const int* in_sizes, int n_in,
                              void* d_out, int out_size) {
    const float* x  = (const float*)d_in[0];
    const float* cb = (const float*)d_in[1];
    float* out = (float*)d_out;

    int N = in_sizes[0] / DDIM;   // 262144
    int K = in_sizes[1] / DDIM;   // 1024

    cudaFuncSetAttribute(vq_main_kernel,
                         cudaFuncAttributeMaxDynamicSharedMemorySize, SMEM_BYTES);
    int prepxSmem = 256 * 68 * 4 + 256 * 16 * 4;
    cudaFuncSetAttribute(prep_x_kernel,
                         cudaFuncAttributeMaxDynamicSharedMemorySize, prepxSmem);

    zero_kernel<<<1, 1>>>();
    prep_cb_kernel<<<(K + 255) / 256, 256>>>(cb, K);
    prep_x_kernel<<<N / 256, 256, prepxSmem>>>(x);
    vq_main_kernel<<<N / BM, NT, SMEM_BYTES>>>(x, cb, out, N, K);
    finalize_kernel<<<1, 256>>>(out, N);
}